// round 1
// baseline (speedup 1.0000x reference)
#include <cuda_runtime.h>
#include <math.h>

#define FRAME_LEN 400
#define HOP 160
#define FFT_LEN 512
#define NBINS 257
#define NMEL 80
#define FB_ELEMS (NBINS * NMEL)   // 20560
#define PREEMPH 0.97f
#define MEL_FLOOR 1.192092955078125e-07f
#define MAX_FRAMES 60000
#define RED_BLOCKS 128

// ---- device scratch (no allocations allowed) ----
__device__ float  g_mel[MAX_FRAMES * NMEL];          // log-mel before normalization
__device__ float2 g_twid[256];                        // e^{-2pi i k/512}
__device__ float  g_psum[RED_BLOCKS * NMEL];
__device__ float  g_psq [RED_BLOCKS * NMEL];
__device__ float  g_mean[NMEL];
__device__ float  g_istd[NMEL];

// ---------------------------------------------------------------------------
__global__ void init_twiddle_kernel() {
    int k = threadIdx.x;           // 256 threads
    double a = -2.0 * 3.14159265358979323846 * (double)k / 512.0;
    g_twid[k] = make_float2((float)cos(a), (float)sin(a));
}

// ---------------------------------------------------------------------------
// Main: frame -> DC removal -> preemph -> window -> 512 FFT -> power -> mel -> log
// 256 threads/block, one frame per grid-stride iteration.
// Dynamic shared layout (floats):
//   fb   [20560]
//   twr/twi packed as float2 tw[256]  (512 floats)
//   x    [400]
//   re   [512]
//   im   [512]
//   spec [257]
//   mpart[240]
//   red  [32]
#define SM_FB     0
#define SM_TW     (SM_FB + FB_ELEMS)          // float2 x 256 => 512 floats
#define SM_X      (SM_TW + 512)
#define SM_RE     (SM_X + FRAME_LEN)
#define SM_IM     (SM_RE + FFT_LEN)
#define SM_SPEC   (SM_IM + FFT_LEN)
#define SM_MPART  (SM_SPEC + NBINS)
#define SM_RED    (SM_MPART + 240)
#define SM_TOTAL  (SM_RED + 32)               // floats

__global__ __launch_bounds__(256, 2)
void melspec_kernel(const float* __restrict__ wav,
                    const float* __restrict__ mel_filters,
                    const float* __restrict__ window,
                    int num_frames) {
    extern __shared__ float smem[];
    float* fb    = smem + SM_FB;
    float2* tw   = (float2*)(smem + SM_TW);
    float* xs    = smem + SM_X;
    float* re    = smem + SM_RE;
    float* im    = smem + SM_IM;
    float* spec  = smem + SM_SPEC;
    float* mpart = smem + SM_MPART;
    float* red   = smem + SM_RED;

    const int tid = threadIdx.x;

    // one-time per-block loads
    for (int i = tid; i < FB_ELEMS; i += 256) fb[i] = mel_filters[i];
    for (int i = tid; i < 256; i += 256)      tw[i] = g_twid[i];
    __shared__ float win_s[FRAME_LEN];
    for (int i = tid; i < FRAME_LEN; i += 256) win_s[i] = window[i];
    __syncthreads();

    const int lane = tid & 31;
    const int warp = tid >> 5;

    for (int f = blockIdx.x; f < num_frames; f += gridDim.x) {
        const float* src = wav + (long long)f * HOP;

        // load + scale, partial sum for DC mean
        float psum = 0.0f;
        for (int n = tid; n < FRAME_LEN; n += 256) {
            float v = src[n] * 32768.0f;
            xs[n] = v;
            psum += v;
        }
        // block reduce psum (8 warps)
        #pragma unroll
        for (int o = 16; o > 0; o >>= 1)
            psum += __shfl_xor_sync(0xffffffffu, psum, o);
        if (lane == 0) red[warp] = psum;
        __syncthreads();
        float mean;
        {
            float s = (lane < 8) ? red[lane] : 0.0f;
            #pragma unroll
            for (int o = 4; o > 0; o >>= 1)
                s += __shfl_xor_sync(0xffffffffu, s, o);
            mean = __shfl_sync(0xffffffffu, s, 0) * (1.0f / FRAME_LEN);
        }

        // zero FFT buffers
        for (int i = tid; i < FFT_LEN; i += 256) { re[i] = 0.0f; im[i] = 0.0f; }
        __syncthreads();

        // preemphasis + window, store bit-reversed
        for (int n = tid; n < FRAME_LEN; n += 256) {
            float xc = xs[n] - mean;
            float v;
            if (n == 0) v = xc * (1.0f - PREEMPH);
            else        v = xc - PREEMPH * (xs[n - 1] - mean);
            v *= win_s[n];
            re[__brev((unsigned)n) >> 23] = v;
        }
        __syncthreads();

        // 9-stage DIT radix-2 FFT, 256 butterflies per stage (one per thread)
        #pragma unroll
        for (int s = 1; s <= 9; ++s) {
            const int half = 1 << (s - 1);
            const int grp  = tid >> (s - 1);
            const int k    = tid & (half - 1);
            const int i1   = (grp << s) + k;
            const int i2   = i1 + half;
            const float2 w = tw[k << (9 - s)];
            float ar = re[i1], ai = im[i1];
            float br = re[i2], bi = im[i2];
            float tr = w.x * br - w.y * bi;
            float ti = w.x * bi + w.y * br;
            re[i1] = ar + tr; im[i1] = ai + ti;
            re[i2] = ar - tr; im[i2] = ai - ti;
            __syncthreads();
        }

        // power spectrum (bins 0..256)
        for (int k = tid; k < NBINS; k += 256)
            spec[k] = re[k] * re[k] + im[k] * im[k];
        __syncthreads();

        // mel dot: 3 k-partitions x 80 bins = 240 active threads
        const int part = tid / NMEL;            // 0..2 (tid<240)
        const int b    = tid - part * NMEL;
        if (part < 3) {
            int k0 = part * 86;
            int k1 = (k0 + 86 < NBINS) ? k0 + 86 : NBINS;
            float acc = 0.0f;
            for (int k = k0; k < k1; ++k)
                acc = fmaf(spec[k], fb[k * NMEL + b], acc);
            mpart[part * NMEL + b] = acc;
        }
        __syncthreads();
        if (tid < NMEL) {
            float dot = mpart[tid] + mpart[NMEL + tid] + mpart[2 * NMEL + tid];
            g_mel[(long long)f * NMEL + tid] = logf(fmaxf(dot, MEL_FLOOR));
        }
        __syncthreads();   // protect shared reuse next iteration
    }
}

// ---------------------------------------------------------------------------
// Stage-1 reduction: per-block fp32 partial sum / sumsq per mel bin.
// blockDim = 320 -> (4 frame-slots) x 80 bins
__global__ void reduce1_kernel(int num_frames) {
    const int tid = threadIdx.x;
    const int b   = tid % NMEL;
    const int fr  = tid / NMEL;   // 0..3
    float s = 0.0f, q = 0.0f;
    for (int f = blockIdx.x * 4 + fr; f < num_frames; f += gridDim.x * 4) {
        float v = g_mel[(long long)f * NMEL + b];
        s += v;
        q += v * v;
    }
    __shared__ float sh_s[320], sh_q[320];
    sh_s[tid] = s; sh_q[tid] = q;
    __syncthreads();
    if (tid < NMEL) {
        float ts = sh_s[tid] + sh_s[tid + 80] + sh_s[tid + 160] + sh_s[tid + 240];
        float tq = sh_q[tid] + sh_q[tid + 80] + sh_q[tid + 160] + sh_q[tid + 240];
        g_psum[blockIdx.x * NMEL + tid] = ts;
        g_psq [blockIdx.x * NMEL + tid] = tq;
    }
}

// Stage-2: fp64 final reduce, mean + inv-std (ddof=1)
__global__ void reduce2_kernel(int num_frames) {
    int b = threadIdx.x;
    if (b >= NMEL) return;
    double s = 0.0, q = 0.0;
    for (int i = 0; i < RED_BLOCKS; ++i) {
        s += (double)g_psum[i * NMEL + b];
        q += (double)g_psq [i * NMEL + b];
    }
    double F = (double)num_frames;
    double mean = s / F;
    double var  = (q - F * mean * mean) / (F - 1.0);
    g_mean[b] = (float)mean;
    g_istd[b] = (float)(1.0 / sqrt(var + 1e-7));
}

// ---------------------------------------------------------------------------
__global__ void normalize_kernel(float* __restrict__ out, int n) {
    for (int i = blockIdx.x * blockDim.x + threadIdx.x; i < n;
         i += gridDim.x * blockDim.x) {
        int b = i % NMEL;
        out[i] = (g_mel[i] - g_mean[b]) * g_istd[b];
    }
}

// ---------------------------------------------------------------------------
extern "C" void kernel_launch(void* const* d_in, const int* in_sizes, int n_in,
                              void* d_out, int out_size) {
    const float* wav = (const float*)d_in[0];
    const float* fb  = (const float*)d_in[1];
    const float* win = (const float*)d_in[2];
    float* out = (float*)d_out;

    int T = in_sizes[0];
    int F = 1 + (T - FRAME_LEN) / HOP;
    if (F > MAX_FRAMES) F = MAX_FRAMES;

    static int smem_set = 0;
    const int smem_bytes = SM_TOTAL * (int)sizeof(float);
    if (!smem_set) {
        cudaFuncSetAttribute(melspec_kernel,
                             cudaFuncAttributeMaxDynamicSharedMemorySize,
                             smem_bytes);
        smem_set = 1;
    }

    init_twiddle_kernel<<<1, 256>>>();
    melspec_kernel<<<592, 256, smem_bytes>>>(wav, fb, win, F);
    reduce1_kernel<<<RED_BLOCKS, 320>>>(F);
    reduce2_kernel<<<1, 128>>>(F);
    normalize_kernel<<<1024, 256>>>(out, F * NMEL);
}

// round 2
// speedup vs baseline: 2.4572x; 2.4572x over previous
#include <cuda_runtime.h>
#include <math.h>

#define FRAME_LEN 400
#define HOP 160
#define FFT_LEN 512
#define NBINS 257
#define NMEL 80
#define FB_ELEMS (NBINS * NMEL)   // 20560
#define PREEMPH 0.97f
#define MEL_FLOOR 1.192092955078125e-07f
#define MAX_FRAMES 60000
#define RED_BLOCKS 128

// ---- device scratch ----
__device__ float  g_spec[MAX_FRAMES * NBINS];        // power spectra
__device__ float  g_mel [MAX_FRAMES * NMEL];         // log-mel
__device__ float2 g_twid[256];
__device__ float  g_psum[RED_BLOCKS * NMEL];
__device__ float  g_psq [RED_BLOCKS * NMEL];
__device__ float  g_mean[NMEL];
__device__ float  g_istd[NMEL];

// ---------------------------------------------------------------------------
__global__ void init_twiddle_kernel() {
    int k = threadIdx.x;
    double a = -2.0 * 3.14159265358979323846 * (double)k / 512.0;
    g_twid[k] = make_float2((float)cos(a), (float)sin(a));
}

// ---------------------------------------------------------------------------
// Kernel A: framing + preemph + window + packed 2-real-in-1-complex FFT
//           + conjugate-symmetry unpack -> power spectra to g_spec.
// 256 threads, 8 frames (4 complex FFTs) per block iteration.
// Skewed smem index phys(i) = i + (i>>5) for conflict-free bitrev scatter.
#define PHYS(i) ((i) + ((i) >> 5))
#define BUFSZ 528   // 512 + 16 skew pad

__global__ __launch_bounds__(256)
void specfft_kernel(const float* __restrict__ wav,
                    const float* __restrict__ window,
                    int num_frames) {
    __shared__ float re[4][BUFSZ];
    __shared__ float im[4][BUFSZ];
    __shared__ float win_s[FRAME_LEN];
    __shared__ float2 tw[256];

    const int tid  = threadIdx.x;
    const int warp = tid >> 5;
    const int lane = tid & 31;

    for (int i = tid; i < FRAME_LEN; i += 256) win_s[i] = window[i];
    if (tid < 256) tw[tid] = g_twid[tid];
    __syncthreads();

    for (int base = blockIdx.x * 8; base < num_frames; base += gridDim.x * 8) {
        // ---- each warp loads one frame into re (even warp) / im (odd warp) ----
        const int f     = base + warp;
        const int buf   = warp >> 1;
        const bool valid = (f < num_frames);
        float* dst = (warp & 1) ? im[buf] : re[buf];
        const float* src = wav + (long long)f * HOP;

        float m = 0.0f;
        if (valid) {
            float s = 0.0f;
            for (int n = lane; n < FRAME_LEN; n += 32) s += src[n];
            #pragma unroll
            for (int o = 16; o > 0; o >>= 1) s += __shfl_xor_sync(0xffffffffu, s, o);
            m = s * (32768.0f / FRAME_LEN);
        }
        const float mc = m * (1.0f - PREEMPH);

        for (int n = lane; n < FFT_LEN; n += 32) {
            float v = 0.0f;
            if (valid && n < FRAME_LEN) {
                if (n == 0) v = (src[0] * 32768.0f - m) * (1.0f - PREEMPH);
                else        v = (src[n] - PREEMPH * src[n - 1]) * 32768.0f - mc;
                v *= win_s[n];
            }
            int j = __brev((unsigned)n) >> 23;
            dst[PHYS(j)] = v;
        }
        __syncthreads();

        // ---- 9-stage radix-2 DIT on 4 complex buffers (same butterfly idx) ----
        #pragma unroll
        for (int s = 1; s <= 9; ++s) {
            const int half = 1 << (s - 1);
            const int grp  = tid >> (s - 1);
            const int k    = tid & (half - 1);
            const int i1   = (grp << s) + k;
            const int i2   = i1 + half;
            const int p1   = PHYS(i1);
            const int p2   = PHYS(i2);
            const float2 w = tw[k << (9 - s)];
            #pragma unroll
            for (int b = 0; b < 4; ++b) {
                float ar = re[b][p1], ai = im[b][p1];
                float br = re[b][p2], bi = im[b][p2];
                float tr = w.x * br - w.y * bi;
                float ti = w.x * bi + w.y * br;
                re[b][p1] = ar + tr; im[b][p1] = ai + ti;
                re[b][p2] = ar - tr; im[b][p2] = ai - ti;
            }
            __syncthreads();
        }

        // ---- unpack: Z = A + iB ; powerA/powerB via conjugate symmetry ----
        {
            const int g  = tid >> 6;        // buffer 0..3
            const int gt = tid & 63;
            const int fA = base + 2 * g;
            const int fB = fA + 1;
            for (int k = gt; k < NBINS; k += 64) {
                const int mm = (FFT_LEN - k) & (FFT_LEN - 1);
                const int pk = PHYS(k), pm = PHYS(mm);
                float zrk = re[g][pk], zik = im[g][pk];
                float zrm = re[g][pm], zim = im[g][pm];
                float ar = zrk + zrm, ai = zik - zim;   // 2*A
                float br = zik + zim, bi = zrk - zrm;   // 2*B (rotated; |.| same)
                float pA = 0.25f * (ar * ar + ai * ai);
                float pB = 0.25f * (br * br + bi * bi);
                if (fA < num_frames) g_spec[(long long)fA * NBINS + k] = pA;
                if (fB < num_frames) g_spec[(long long)fB * NBINS + k] = pB;
            }
        }
        __syncthreads();
    }
}

// ---------------------------------------------------------------------------
// Kernel B: mel GEMM  g_mel[f][b] = log(max(sum_k spec[f][k]*fb[k][b], floor))
// Block tile: 128 frames x 80 bins, k-tiles of 16, fb resident in smem.
// 256 threads: tx = tid%16 (frame groups), ty = tid/16 (bin groups),
// each thread: 8 frames x 5 bins accumulators.
#define BT_F 128
#define KT   16
#define SPEC_LD 129   // padded row stride

__global__ __launch_bounds__(256, 2)
void melgemm_kernel(const float* __restrict__ mel_filters, int num_frames) {
    extern __shared__ float sm[];
    float* fb_s   = sm;                   // [257*80]
    float* spec_t = sm + FB_ELEMS;        // [KT][SPEC_LD]

    const int tid = threadIdx.x;
    const int tx  = tid & 15;
    const int ty  = tid >> 4;
    const int f0  = blockIdx.x * BT_F;

    for (int i = tid; i < FB_ELEMS; i += 256) fb_s[i] = mel_filters[i];

    float acc[8][5];
    #pragma unroll
    for (int i = 0; i < 8; ++i)
        #pragma unroll
        for (int j = 0; j < 5; ++j) acc[i][j] = 0.0f;

    // 16 full k-tiles (k = 0..255)
    for (int t = 0; t < 16; ++t) {
        const int k0 = t * KT;
        __syncthreads();
        #pragma unroll
        for (int it = 0; it < 8; ++it) {
            int e = tid + it * 256;
            int k = e & 15, ff = e >> 4;
            int f = f0 + ff;
            spec_t[k * SPEC_LD + ff] =
                (f < num_frames) ? g_spec[(long long)f * NBINS + k0 + k] : 0.0f;
        }
        __syncthreads();
        #pragma unroll
        for (int kk = 0; kk < KT; ++kk) {
            float w[5];
            #pragma unroll
            for (int j = 0; j < 5; ++j)
                w[j] = fb_s[(k0 + kk) * NMEL + ty + 16 * j];
            #pragma unroll
            for (int i = 0; i < 8; ++i) {
                float s = spec_t[kk * SPEC_LD + tx + 16 * i];
                #pragma unroll
                for (int j = 0; j < 5; ++j)
                    acc[i][j] = fmaf(s, w[j], acc[i][j]);
            }
        }
    }

    // epilogue: k = 256
    {
        float w[5];
        #pragma unroll
        for (int j = 0; j < 5; ++j)
            w[j] = fb_s[256 * NMEL + ty + 16 * j];
        #pragma unroll
        for (int i = 0; i < 8; ++i) {
            int f = f0 + tx + 16 * i;
            float s = (f < num_frames) ? g_spec[(long long)f * NBINS + 256] : 0.0f;
            #pragma unroll
            for (int j = 0; j < 5; ++j)
                acc[i][j] = fmaf(s, w[j], acc[i][j]);
        }
    }

    #pragma unroll
    for (int i = 0; i < 8; ++i) {
        int f = f0 + tx + 16 * i;
        if (f < num_frames) {
            #pragma unroll
            for (int j = 0; j < 5; ++j)
                g_mel[(long long)f * NMEL + ty + 16 * j] =
                    logf(fmaxf(acc[i][j], MEL_FLOOR));
        }
    }
}

// ---------------------------------------------------------------------------
__global__ void reduce1_kernel(int num_frames) {
    const int tid = threadIdx.x;
    const int b   = tid % NMEL;
    const int fr  = tid / NMEL;   // 0..3
    float s = 0.0f, q = 0.0f;
    for (int f = blockIdx.x * 4 + fr; f < num_frames; f += gridDim.x * 4) {
        float v = g_mel[(long long)f * NMEL + b];
        s += v;
        q += v * v;
    }
    __shared__ float sh_s[320], sh_q[320];
    sh_s[tid] = s; sh_q[tid] = q;
    __syncthreads();
    if (tid < NMEL) {
        float ts = sh_s[tid] + sh_s[tid + 80] + sh_s[tid + 160] + sh_s[tid + 240];
        float tq = sh_q[tid] + sh_q[tid + 80] + sh_q[tid + 160] + sh_q[tid + 240];
        g_psum[blockIdx.x * NMEL + tid] = ts;
        g_psq [blockIdx.x * NMEL + tid] = tq;
    }
}

__global__ void reduce2_kernel(int num_frames) {
    int b = threadIdx.x;
    if (b >= NMEL) return;
    double s = 0.0, q = 0.0;
    for (int i = 0; i < RED_BLOCKS; ++i) {
        s += (double)g_psum[i * NMEL + b];
        q += (double)g_psq [i * NMEL + b];
    }
    double F = (double)num_frames;
    double mean = s / F;
    double var  = (q - F * mean * mean) / (F - 1.0);
    g_mean[b] = (float)mean;
    g_istd[b] = (float)(1.0 / sqrt(var + 1e-7));
}

__global__ void normalize_kernel(float* __restrict__ out, int n) {
    for (int i = blockIdx.x * blockDim.x + threadIdx.x; i < n;
         i += gridDim.x * blockDim.x) {
        int b = i % NMEL;
        out[i] = (g_mel[i] - g_mean[b]) * g_istd[b];
    }
}

// ---------------------------------------------------------------------------
extern "C" void kernel_launch(void* const* d_in, const int* in_sizes, int n_in,
                              void* d_out, int out_size) {
    const float* wav = (const float*)d_in[0];
    const float* fb  = (const float*)d_in[1];
    const float* win = (const float*)d_in[2];
    float* out = (float*)d_out;

    int T = in_sizes[0];
    int F = 1 + (T - FRAME_LEN) / HOP;
    if (F > MAX_FRAMES) F = MAX_FRAMES;

    static int attr_set = 0;
    const int smemB = (FB_ELEMS + KT * SPEC_LD) * (int)sizeof(float);
    if (!attr_set) {
        cudaFuncSetAttribute(melgemm_kernel,
                             cudaFuncAttributeMaxDynamicSharedMemorySize, smemB);
        attr_set = 1;
    }

    init_twiddle_kernel<<<1, 256>>>();
    specfft_kernel<<<1184, 256>>>(wav, win, F);
    melgemm_kernel<<<(F + BT_F - 1) / BT_F, 256, smemB>>>(fb, F);
    reduce1_kernel<<<RED_BLOCKS, 320>>>(F);
    reduce2_kernel<<<1, 128>>>(F);
    normalize_kernel<<<1024, 256>>>(out, F * NMEL);
}

// round 4
// speedup vs baseline: 2.6037x; 1.0596x over previous
#include <cuda_runtime.h>
#include <math.h>

#define FRAME_LEN 400
#define HOP 160
#define FFT_LEN 512
#define NBINS 257
#define NMEL 80
#define PREEMPH 0.97f
#define MEL_FLOOR 1.192092955078125e-07f
#define MAX_FRAMES 60000
#define ABLOCKS 1184
#define WCAP 2048

// ---- device scratch ----
__device__ float  g_mel [MAX_FRAMES * NMEL];
__device__ float2 g_twid[256];
__device__ float  g_psum[ABLOCKS * NMEL];
__device__ float  g_psq [ABLOCKS * NMEL];
__device__ float  g_mean[NMEL];
__device__ float  g_istd[NMEL];
// compacted filterbank
__device__ int    g_klo[NMEL];
__device__ int    g_wid[NMEL];
__device__ int    g_off[NMEL];
__device__ float  g_wts[WCAP];

// ---------------------------------------------------------------------------
__global__ void init_twiddle_kernel() {
    int k = threadIdx.x;
    double a = -2.0 * 3.14159265358979323846 * (double)k / 512.0;
    g_twid[k] = make_float2((float)cos(a), (float)sin(a));
}

// ---------------------------------------------------------------------------
// Compact the triangular filterbank. One thread per mel bin scans all 257
// rows (init-only cost) — trivially correct coverage.
__global__ void init_compact_kernel(const float* __restrict__ fb) {
    __shared__ int wid_sh[NMEL];
    __shared__ int off_sh[NMEL];
    const int b = threadIdx.x;

    if (b < NMEL) {
        int lo = -1, hi = -2;
        for (int k = 0; k < NBINS; ++k) {
            if (fb[k * NMEL + b] != 0.0f) { if (lo < 0) lo = k; hi = k; }
        }
        int w = hi - lo + 1;          // 0 if column is all-zero
        if (w < 0) w = 0;
        g_klo[b]  = (lo < 0) ? 0 : lo;
        wid_sh[b] = w;
    }
    __syncthreads();
    if (b == 0) {
        int off = 0;
        for (int i = 0; i < NMEL; ++i) {
            int w = wid_sh[i];
            if (off + w > WCAP) w = WCAP - off;   // safety clamp
            if (w < 0) w = 0;
            wid_sh[i] = w;
            off_sh[i] = off;
            off += w;
        }
    }
    __syncthreads();
    if (b < NMEL) {
        int off = off_sh[b], lo = g_klo[b], w = wid_sh[b];
        g_wid[b] = w;
        g_off[b] = off;
        for (int i = 0; i < w; ++i)
            g_wts[off + i] = fb[(lo + i) * NMEL + b];
    }
}

// ---------------------------------------------------------------------------
// Fused: framing + preemph + window + packed 2-real-in-1-complex FFT
//        + conj-symmetry unpack -> power in smem -> sparse mel + log -> g_mel
//        + deterministic per-block per-bin sum/sumsq partials.
#define PHYS(i) ((i) + ((i) >> 5))
#define BUFSZ 528
#define SPEC_LD 264

__global__ __launch_bounds__(256)
void fused_kernel(const float* __restrict__ wav,
                  const float* __restrict__ window,
                  int num_frames) {
    __shared__ float  re[4][BUFSZ];
    __shared__ float  im[4][BUFSZ];
    __shared__ float  win_s[FRAME_LEN];
    __shared__ float2 tw[256];
    __shared__ float  spec_s[8][SPEC_LD];
    __shared__ float  mel_s[8 * NMEL];
    __shared__ float  wts_s[WCAP];
    __shared__ int    klo_s[NMEL], wid_s[NMEL], off_s[NMEL];

    const int tid  = threadIdx.x;
    const int warp = tid >> 5;
    const int lane = tid & 31;

    for (int i = tid; i < FRAME_LEN; i += 256) win_s[i] = window[i];
    tw[tid] = g_twid[tid];
    if (tid < NMEL) {
        klo_s[tid] = g_klo[tid];
        wid_s[tid] = g_wid[tid];
        off_s[tid] = g_off[tid];
    }
    __syncthreads();
    {
        int tot = off_s[NMEL - 1] + wid_s[NMEL - 1];
        for (int i = tid; i < tot; i += 256) wts_s[i] = g_wts[i];
    }
    // (wts_s reads are separated from these writes by the FFT barriers below)

    float acc_sum = 0.0f, acc_sq = 0.0f;   // bin `tid` stats (tid < 80)

    for (int base = blockIdx.x * 8; base < num_frames; base += gridDim.x * 8) {
        // ---- each warp loads one frame into re (even warp) / im (odd warp)
        const int f     = base + warp;
        const int buf   = warp >> 1;
        const bool valid = (f < num_frames);
        float* dst = (warp & 1) ? im[buf] : re[buf];
        const float* src = wav + (long long)f * HOP;

        float m = 0.0f;
        if (valid) {
            float s = 0.0f;
            for (int n = lane; n < FRAME_LEN; n += 32) s += src[n];
            #pragma unroll
            for (int o = 16; o > 0; o >>= 1) s += __shfl_xor_sync(0xffffffffu, s, o);
            m = s * (32768.0f / FRAME_LEN);
        }
        const float mc = m * (1.0f - PREEMPH);

        for (int n = lane; n < FFT_LEN; n += 32) {
            float v = 0.0f;
            if (valid && n < FRAME_LEN) {
                if (n == 0) v = (src[0] * 32768.0f - m) * (1.0f - PREEMPH);
                else        v = (src[n] - PREEMPH * src[n - 1]) * 32768.0f - mc;
                v *= win_s[n];
            }
            int j = __brev((unsigned)n) >> 23;
            dst[PHYS(j)] = v;
        }
        __syncthreads();

        // ---- 9-stage radix-2 DIT on 4 complex buffers
        #pragma unroll
        for (int s = 1; s <= 9; ++s) {
            const int half = 1 << (s - 1);
            const int grp  = tid >> (s - 1);
            const int k    = tid & (half - 1);
            const int i1   = (grp << s) + k;
            const int i2   = i1 + half;
            const int p1   = PHYS(i1);
            const int p2   = PHYS(i2);
            const float2 w = tw[k << (9 - s)];
            #pragma unroll
            for (int b = 0; b < 4; ++b) {
                float ar = re[b][p1], ai = im[b][p1];
                float br = re[b][p2], bi = im[b][p2];
                float tr = w.x * br - w.y * bi;
                float ti = w.x * bi + w.y * br;
                re[b][p1] = ar + tr; im[b][p1] = ai + ti;
                re[b][p2] = ar - tr; im[b][p2] = ai - ti;
            }
            __syncthreads();
        }

        // ---- unpack to power spectra in smem
        {
            const int g  = tid >> 6;
            const int gt = tid & 63;
            for (int k = gt; k < NBINS; k += 64) {
                const int mm = (FFT_LEN - k) & (FFT_LEN - 1);
                const int pk = PHYS(k), pm = PHYS(mm);
                float zrk = re[g][pk], zik = im[g][pk];
                float zrm = re[g][pm], zim = im[g][pm];
                float ar = zrk + zrm, ai = zik - zim;
                float br = zik + zim, bi = zrk - zrm;
                spec_s[2 * g][k]     = 0.25f * (ar * ar + ai * ai);
                spec_s[2 * g + 1][k] = 0.25f * (br * br + bi * bi);
            }
        }
        __syncthreads();

        // ---- sparse mel + log: 640 tasks = 8 frames x 80 bins
        #pragma unroll
        for (int it = 0; it < 3; ++it) {
            int t = tid + it * 256;
            if (t < 8 * NMEL) {
                int fr = t / NMEL;
                int b  = t - fr * NMEL;
                int f2 = base + fr;
                float lv = 0.0f;
                if (f2 < num_frames) {
                    int lo = klo_s[b], w = wid_s[b], off = off_s[b];
                    float acc = 0.0f;
                    for (int i = 0; i < w; ++i)
                        acc = fmaf(spec_s[fr][lo + i], wts_s[off + i], acc);
                    lv = logf(fmaxf(acc, MEL_FLOOR));
                    g_mel[(long long)f2 * NMEL + b] = lv;
                }
                mel_s[t] = lv;
            }
        }
        __syncthreads();

        // ---- per-bin stats (thread tid owns bin tid; fixed order = deterministic)
        if (tid < NMEL) {
            #pragma unroll
            for (int fr = 0; fr < 8; ++fr) {
                if (base + fr < num_frames) {
                    float v = mel_s[fr * NMEL + tid];
                    acc_sum += v;
                    acc_sq  += v * v;
                }
            }
        }
        __syncthreads();
    }

    if (tid < NMEL) {
        g_psum[blockIdx.x * NMEL + tid] = acc_sum;
        g_psq [blockIdx.x * NMEL + tid] = acc_sq;
    }
}

// ---------------------------------------------------------------------------
// Final stats: 1024 threads, 12 chunks x 80 bins, fp64 combine.
// var clamped to >= 0 (jnp.var is mean-of-squared-deviations: non-negative).
__global__ void reduce2_kernel(int num_frames) {
    __shared__ double sh_s[12 * NMEL], sh_q[12 * NMEL];
    const int tid   = threadIdx.x;
    const int b     = tid % NMEL;
    const int chunk = tid / NMEL;
    if (chunk < 12) {
        double s = 0.0, q = 0.0;
        for (int i = chunk; i < ABLOCKS; i += 12) {
            s += (double)g_psum[i * NMEL + b];
            q += (double)g_psq [i * NMEL + b];
        }
        sh_s[chunk * NMEL + b] = s;
        sh_q[chunk * NMEL + b] = q;
    }
    __syncthreads();
    if (tid < NMEL) {
        double s = 0.0, q = 0.0;
        #pragma unroll
        for (int c = 0; c < 12; ++c) {
            s += sh_s[c * NMEL + tid];
            q += sh_q[c * NMEL + tid];
        }
        double F = (double)num_frames;
        double mean = s / F;
        double var  = (q - F * mean * mean) / (F - 1.0);
        if (var < 0.0) var = 0.0;
        g_mean[tid] = (float)mean;
        g_istd[tid] = (float)(1.0 / sqrt(var + 1e-7));
    }
}

// ---------------------------------------------------------------------------
__global__ void normalize_kernel(float4* __restrict__ out, int n4) {
    __shared__ float mean_s[NMEL], istd_s[NMEL];
    if (threadIdx.x < NMEL) {
        mean_s[threadIdx.x] = g_mean[threadIdx.x];
        istd_s[threadIdx.x] = g_istd[threadIdx.x];
    }
    __syncthreads();
    const float4* mel4 = (const float4*)g_mel;
    for (int i = blockIdx.x * blockDim.x + threadIdx.x; i < n4;
         i += gridDim.x * blockDim.x) {
        int b = (i % 20) * 4;
        float4 v = mel4[i];
        float4 r;
        r.x = (v.x - mean_s[b    ]) * istd_s[b    ];
        r.y = (v.y - mean_s[b + 1]) * istd_s[b + 1];
        r.z = (v.z - mean_s[b + 2]) * istd_s[b + 2];
        r.w = (v.w - mean_s[b + 3]) * istd_s[b + 3];
        out[i] = r;
    }
}

// ---------------------------------------------------------------------------
extern "C" void kernel_launch(void* const* d_in, const int* in_sizes, int n_in,
                              void* d_out, int out_size) {
    const float* wav = (const float*)d_in[0];
    const float* fb  = (const float*)d_in[1];
    const float* win = (const float*)d_in[2];
    float* out = (float*)d_out;

    int T = in_sizes[0];
    int F = 1 + (T - FRAME_LEN) / HOP;
    if (F > MAX_FRAMES) F = MAX_FRAMES;

    init_twiddle_kernel<<<1, 256>>>();
    init_compact_kernel<<<1, 128>>>(fb);
    fused_kernel<<<ABLOCKS, 256>>>(wav, win, F);
    reduce2_kernel<<<1, 1024>>>(F);
    normalize_kernel<<<1024, 256>>>((float4*)out, F * NMEL / 4);
}

// round 5
// speedup vs baseline: 4.5708x; 1.7555x over previous
#include <cuda_runtime.h>
#include <math.h>

#define FRAME_LEN 400
#define HOP 160
#define FFT_LEN 512
#define NBINS 257
#define NMEL 80
#define PREEMPH 0.97f
#define MEL_FLOOR 1.192092955078125e-07f
#define MAX_FRAMES 60000
#define ABLOCKS 592
#define WCAP 2048

// ---- device scratch ----
__device__ float  g_mel [MAX_FRAMES * NMEL];
__device__ float2 g_twid[512];
__device__ float  g_psum[ABLOCKS * NMEL];
__device__ float  g_psq [ABLOCKS * NMEL];
__device__ float  g_mean[NMEL];
__device__ float  g_istd[NMEL];
__device__ int    g_klo[NMEL];
__device__ int    g_wid[NMEL];
__device__ int    g_off[NMEL];
__device__ float  g_wts[WCAP];

// ---------------------------------------------------------------------------
__global__ void init_twiddle_kernel() {
    int k = threadIdx.x;   // 512 threads
    double a = -2.0 * 3.14159265358979323846 * (double)k / 512.0;
    g_twid[k] = make_float2((float)cos(a), (float)sin(a));
}

// ---------------------------------------------------------------------------
// Compact triangular filterbank: one thread per bin scans all 257 rows.
__global__ void init_compact_kernel(const float* __restrict__ fb) {
    __shared__ int wid_sh[NMEL];
    __shared__ int off_sh[NMEL];
    const int b = threadIdx.x;

    if (b < NMEL) {
        int lo = -1, hi = -2;
        for (int k = 0; k < NBINS; ++k) {
            if (fb[k * NMEL + b] != 0.0f) { if (lo < 0) lo = k; hi = k; }
        }
        int w = hi - lo + 1;
        if (w < 0) w = 0;
        g_klo[b]  = (lo < 0) ? 0 : lo;
        wid_sh[b] = w;
    }
    __syncthreads();
    if (b == 0) {
        int off = 0;
        for (int i = 0; i < NMEL; ++i) {
            int w = wid_sh[i];
            if (off + w > WCAP) w = WCAP - off;
            if (w < 0) w = 0;
            wid_sh[i] = w;
            off_sh[i] = off;
            off += w;
        }
    }
    __syncthreads();
    if (b < NMEL) {
        int off = off_sh[b], lo = g_klo[b], w = wid_sh[b];
        g_wid[b] = w;
        g_off[b] = off;
        for (int i = 0; i < w; ++i)
            g_wts[off + i] = fb[(lo + i) * NMEL + b];
    }
}

// ---------------------------------------------------------------------------
#define PHYS8(i) ((i) + ((i) >> 3))
#define BUF 576   // 512 + 64 pad
#define SPEC_LD 264

#define FFT2(ar,ai,br,bi) { float tr_=ar, ti_=ai; ar=tr_+br; ai=ti_+bi; br=tr_-br; bi=ti_-bi; }
#define CMUL(xr,xi,wr,wi) { float tr_=xr; xr=tr_*(wr)-xi*(wi); xi=tr_*(wi)+xi*(wr); }
#define RSQ2 0.70710678118654752440f

// 8-pt DIF DFT in registers. Output: v[m] holds X[brev3(m)], brev3={0,4,2,6,1,5,3,7}
__device__ __forceinline__ void fft8(float* vr, float* vi) {
    FFT2(vr[0], vi[0], vr[4], vi[4]);
    FFT2(vr[1], vi[1], vr[5], vi[5]);
    FFT2(vr[2], vi[2], vr[6], vi[6]);
    FFT2(vr[3], vi[3], vr[7], vi[7]);
    CMUL(vr[5], vi[5],  RSQ2, -RSQ2);          // W8^1
    CMUL(vr[6], vi[6],  0.0f, -1.0f);          // W8^2 = -i
    CMUL(vr[7], vi[7], -RSQ2, -RSQ2);          // W8^3
    FFT2(vr[0], vi[0], vr[2], vi[2]);
    FFT2(vr[1], vi[1], vr[3], vi[3]);
    FFT2(vr[4], vi[4], vr[6], vi[6]);
    FFT2(vr[5], vi[5], vr[7], vi[7]);
    CMUL(vr[3], vi[3], 0.0f, -1.0f);           // W4^1 = -i
    CMUL(vr[7], vi[7], 0.0f, -1.0f);
    FFT2(vr[0], vi[0], vr[1], vi[1]);
    FFT2(vr[2], vi[2], vr[3], vi[3]);
    FFT2(vr[4], vi[4], vr[5], vi[5]);
    FFT2(vr[6], vi[6], vr[7], vi[7]);
}

// Fused: framing + preemph + window + packed Stockham radix-8 FFT (3 passes)
//        + conj-symmetry unpack -> power -> sparse mel + log + stats partials.
__global__ __launch_bounds__(256)
void fused_kernel(const float* __restrict__ wav,
                  const float* __restrict__ window,
                  int num_frames) {
    __shared__ float  re[4][BUF];
    __shared__ float  im[4][BUF];
    __shared__ float  win_s[FRAME_LEN];
    __shared__ float2 tw[512];
    __shared__ float  spec_s[8][SPEC_LD];
    __shared__ float  mel_s[8 * NMEL];
    __shared__ float  wts_s[WCAP];
    __shared__ int    klo_s[NMEL], wid_s[NMEL], off_s[NMEL];

    const int tid  = threadIdx.x;
    const int warp = tid >> 5;
    const int lane = tid & 31;

    for (int i = tid; i < FRAME_LEN; i += 256) win_s[i] = window[i];
    tw[tid] = g_twid[tid];
    tw[tid + 256] = g_twid[tid + 256];
    if (tid < NMEL) {
        klo_s[tid] = g_klo[tid];
        wid_s[tid] = g_wid[tid];
        off_s[tid] = g_off[tid];
    }
    __syncthreads();
    {
        int tot = off_s[NMEL - 1] + wid_s[NMEL - 1];
        for (int i = tid; i < tot; i += 256) wts_s[i] = g_wts[i];
    }

    const int g = tid >> 6;     // FFT buffer 0..3
    const int j = tid & 63;     // butterfly lane within FFT

    float acc_sum = 0.0f, acc_sq = 0.0f;

    for (int base = blockIdx.x * 8; base < num_frames; base += gridDim.x * 8) {
        // ---- load: warp w -> frame base+w, even->re, odd->im of buffer w>>1
        const int f     = base + warp;
        const int buf   = warp >> 1;
        const bool valid = (f < num_frames);
        float* dst = (warp & 1) ? im[buf] : re[buf];
        const float* src = wav + (long long)f * HOP;

        float m = 0.0f;
        if (valid) {
            float s = 0.0f;
            for (int n = lane; n < FRAME_LEN; n += 32) s += src[n];
            #pragma unroll
            for (int o = 16; o > 0; o >>= 1) s += __shfl_xor_sync(0xffffffffu, s, o);
            m = s * (32768.0f / FRAME_LEN);
        }
        const float mc = m * (1.0f - PREEMPH);

        for (int n = lane; n < FFT_LEN; n += 32) {
            float v = 0.0f;
            if (valid && n < FRAME_LEN) {
                if (n == 0) v = (src[0] * 32768.0f - m) * (1.0f - PREEMPH);
                else        v = (src[n] - PREEMPH * src[n - 1]) * 32768.0f - mc;
                v *= win_s[n];
            }
            dst[PHYS8(n)] = v;      // natural order — Stockham needs no bitrev
        }
        __syncthreads();

        float vr[8], vi[8];

        // ---- pass 1: Ns=1 (no twiddle); idxD = 8j
        #pragma unroll
        for (int r = 0; r < 8; ++r) {
            int a = j + (r << 6);
            vr[r] = re[g][PHYS8(a)]; vi[r] = im[g][PHYS8(a)];
        }
        fft8(vr, vi);
        __syncthreads();
        {
            const int d = j << 3;
            // v[m] = X[brev3(m)] -> write at idxD + brev3(m)*Ns
            #pragma unroll
            for (int mth = 0; mth < 8; ++mth) {
                const int BRv[8] = {0, 4, 2, 6, 1, 5, 3, 7};
                int a = d + BRv[mth];
                re[g][PHYS8(a)] = vr[mth]; im[g][PHYS8(a)] = vi[mth];
            }
        }
        __syncthreads();

        // ---- pass 2: Ns=8; q=j&7; twiddle idx = 8*r*q; idxD = (j>>3)*64 + q
        {
            const int q = j & 7;
            #pragma unroll
            for (int r = 0; r < 8; ++r) {
                int a = j + (r << 6);
                vr[r] = re[g][PHYS8(a)]; vi[r] = im[g][PHYS8(a)];
                if (r) {
                    float2 w = tw[(r * q) << 3];
                    CMUL(vr[r], vi[r], w.x, w.y);
                }
            }
            fft8(vr, vi);
            __syncthreads();
            const int d = ((j >> 3) << 6) + q;
            #pragma unroll
            for (int mth = 0; mth < 8; ++mth) {
                const int BRv[8] = {0, 4, 2, 6, 1, 5, 3, 7};
                int a = d + (BRv[mth] << 3);
                re[g][PHYS8(a)] = vr[mth]; im[g][PHYS8(a)] = vi[mth];
            }
        }
        __syncthreads();

        // ---- pass 3: Ns=64; q=j; twiddle idx = r*j; idxD = j
        {
            #pragma unroll
            for (int r = 0; r < 8; ++r) {
                int a = j + (r << 6);
                vr[r] = re[g][PHYS8(a)]; vi[r] = im[g][PHYS8(a)];
                if (r) {
                    float2 w = tw[r * j];
                    CMUL(vr[r], vi[r], w.x, w.y);
                }
            }
            fft8(vr, vi);
            __syncthreads();
            #pragma unroll
            for (int mth = 0; mth < 8; ++mth) {
                const int BRv[8] = {0, 4, 2, 6, 1, 5, 3, 7};
                int a = j + (BRv[mth] << 6);
                re[g][PHYS8(a)] = vr[mth]; im[g][PHYS8(a)] = vi[mth];
            }
        }
        __syncthreads();

        // ---- unpack to power spectra (conjugate symmetry; Z = A + iB)
        for (int k = j; k < NBINS; k += 64) {
            const int mm = (FFT_LEN - k) & (FFT_LEN - 1);
            const int pk = PHYS8(k), pm = PHYS8(mm);
            float zrk = re[g][pk], zik = im[g][pk];
            float zrm = re[g][pm], zim = im[g][pm];
            float ar = zrk + zrm, ai = zik - zim;
            float br = zik + zim, bi = zrk - zrm;
            spec_s[2 * g][k]     = 0.25f * (ar * ar + ai * ai);
            spec_s[2 * g + 1][k] = 0.25f * (br * br + bi * bi);
        }
        __syncthreads();

        // ---- sparse mel + log: 640 tasks = 8 frames x 80 bins
        #pragma unroll
        for (int it = 0; it < 3; ++it) {
            int t = tid + it * 256;
            if (t < 8 * NMEL) {
                int fr = t / NMEL;
                int b  = t - fr * NMEL;
                int f2 = base + fr;
                float lv = 0.0f;
                if (f2 < num_frames) {
                    int lo = klo_s[b], w = wid_s[b], off = off_s[b];
                    float acc = 0.0f;
                    for (int i = 0; i < w; ++i)
                        acc = fmaf(spec_s[fr][lo + i], wts_s[off + i], acc);
                    lv = logf(fmaxf(acc, MEL_FLOOR));
                    g_mel[(long long)f2 * NMEL + b] = lv;
                }
                mel_s[t] = lv;
            }
        }
        __syncthreads();

        // ---- per-bin stats, deterministic fixed order
        if (tid < NMEL) {
            #pragma unroll
            for (int fr = 0; fr < 8; ++fr) {
                if (base + fr < num_frames) {
                    float v = mel_s[fr * NMEL + tid];
                    acc_sum += v;
                    acc_sq  += v * v;
                }
            }
        }
        __syncthreads();
    }

    if (tid < NMEL) {
        g_psum[blockIdx.x * NMEL + tid] = acc_sum;
        g_psq [blockIdx.x * NMEL + tid] = acc_sq;
    }
}

// ---------------------------------------------------------------------------
// One block per mel bin: fp64 strided accumulate + deterministic tree reduce.
__global__ void reduce2_kernel(int num_frames) {
    __shared__ double sh_s[128], sh_q[128];
    const int b = blockIdx.x;
    const int t = threadIdx.x;
    double s = 0.0, q = 0.0;
    for (int i = t; i < ABLOCKS; i += 128) {
        s += (double)g_psum[i * NMEL + b];
        q += (double)g_psq [i * NMEL + b];
    }
    sh_s[t] = s; sh_q[t] = q;
    __syncthreads();
    #pragma unroll
    for (int o = 64; o > 0; o >>= 1) {
        if (t < o) { sh_s[t] += sh_s[t + o]; sh_q[t] += sh_q[t + o]; }
        __syncthreads();
    }
    if (t == 0) {
        double F = (double)num_frames;
        double mean = sh_s[0] / F;
        double var  = (sh_q[0] - F * mean * mean) / (F - 1.0);
        if (var < 0.0) var = 0.0;
        g_mean[b] = (float)mean;
        g_istd[b] = (float)(1.0 / sqrt(var + 1e-7));
    }
}

// ---------------------------------------------------------------------------
__global__ void normalize_kernel(float4* __restrict__ out, int n4) {
    __shared__ float mean_s[NMEL], istd_s[NMEL];
    if (threadIdx.x < NMEL) {
        mean_s[threadIdx.x] = g_mean[threadIdx.x];
        istd_s[threadIdx.x] = g_istd[threadIdx.x];
    }
    __syncthreads();
    const float4* mel4 = (const float4*)g_mel;
    for (int i = blockIdx.x * blockDim.x + threadIdx.x; i < n4;
         i += gridDim.x * blockDim.x) {
        int b = (i % 20) * 4;
        float4 v = mel4[i];
        float4 r;
        r.x = (v.x - mean_s[b    ]) * istd_s[b    ];
        r.y = (v.y - mean_s[b + 1]) * istd_s[b + 1];
        r.z = (v.z - mean_s[b + 2]) * istd_s[b + 2];
        r.w = (v.w - mean_s[b + 3]) * istd_s[b + 3];
        out[i] = r;
    }
}

// ---------------------------------------------------------------------------
extern "C" void kernel_launch(void* const* d_in, const int* in_sizes, int n_in,
                              void* d_out, int out_size) {
    const float* wav = (const float*)d_in[0];
    const float* fb  = (const float*)d_in[1];
    const float* win = (const float*)d_in[2];
    float* out = (float*)d_out;

    int T = in_sizes[0];
    int F = 1 + (T - FRAME_LEN) / HOP;
    if (F > MAX_FRAMES) F = MAX_FRAMES;

    init_twiddle_kernel<<<1, 512>>>();
    init_compact_kernel<<<1, 128>>>(fb);
    fused_kernel<<<ABLOCKS, 256>>>(wav, win, F);
    reduce2_kernel<<<NMEL, 128>>>(F);
    normalize_kernel<<<1024, 256>>>((float4*)out, F * NMEL / 4);
}